// round 5
// baseline (speedup 1.0000x reference)
#include <cuda_runtime.h>
#include <math.h>

#define BB 2
#define C 19
#define CP 20             // padded channels
#define H 128
#define W 128
#define HW (H*W)          // 16384
#define CF 256
#define SH 64
#define SW 64
#define SP (SH*SW)        // 4096
#define N2 (BB*SP)        // 8192
#define NCHUNK 8          // feature channel chunks of 32
#define NBLK 512          // main-kernel blocks (64 pixels each)

// Scratch (static device globals; no allocations)
__device__ float  g_prob2[BB*HW*CP];     // padded probs [b*HW+p][20], [19]=0
__device__ float  g_spart[NCHUNK*5*N2];  // [chunk*5+dir][b*SP+s]; dir 0=self 1=E 2=SW 3=S 4=SE
__device__ float  g_sim[9*N2];           // [k][b*SP+s]
__device__ double g_partial[3*NBLK];
__device__ int    g_count = 0;

// ---------------- K1: softmax -> padded [pixel][20] layout ----------------
__global__ void k_softmax(const float* __restrict__ logits) {
    int idx = blockIdx.x * blockDim.x + threadIdx.x;   // over B*H*W
    if (idx >= BB*HW) return;
    int b = idx >> 14;
    int p = idx & (HW - 1);
    const float* x = logits + (size_t)b * C * HW + p;
    float v[CP];
    float m = -1e30f;
    #pragma unroll
    for (int c = 0; c < C; c++) { v[c] = x[(size_t)c * HW]; m = fmaxf(m, v[c]); }
    float s = 0.f;
    #pragma unroll
    for (int c = 0; c < C; c++) { v[c] = expf(v[c] - m); s += v[c]; }
    float inv = 1.f / s;
    #pragma unroll
    for (int c = 0; c < C; c++) v[c] *= inv;
    v[19] = 0.f;
    float4* o = reinterpret_cast<float4*>(g_prob2 + (size_t)idx * CP);
    #pragma unroll
    for (int q = 0; q < 5; q++)
        o[q] = make_float4(v[4*q], v[4*q+1], v[4*q+2], v[4*q+3]);
}

// ------- K2: per-(source,32ch-chunk) stencil partial distances -------
__global__ void k_simpart(const float* __restrict__ feats) {
    int idx   = blockIdx.x * blockDim.x + threadIdx.x;   // b*SP+s
    int chunk = blockIdx.y;
    int b  = idx >> 12;
    int s  = idx & (SP - 1);
    int sh = s >> 6, sw = s & 63;

    bool eOK = (sw < SW-1), sOK = (sh < SH-1), wOK = (sw > 0);
    int dE  = eOK ? 1 : 0;
    int dSW = (sOK && wOK) ? (SW - 1) : 0;
    int dS  = sOK ? SW : 0;
    int dSE = (sOK && eOK) ? (SW + 1) : 0;

    const float* fb = feats + ((size_t)b * CF + chunk * 32) * SP + s;
    float a0 = 0.f, a1 = 0.f, a2 = 0.f, a3 = 0.f, a4 = 0.f;
    #pragma unroll
    for (int ch = 0; ch < 32; ch++) {
        const float* fp = fb + (size_t)ch * SP;
        float f = fp[0];
        float d;
        a0 += f * f;
        d = f - fp[dE];  a1 += d * d;
        d = f - fp[dSW]; a2 += d * d;
        d = f - fp[dS];  a3 += d * d;
        d = f - fp[dSE]; a4 += d * d;
    }
    g_spart[(chunk*5 + 0) * N2 + idx] = a0;
    g_spart[(chunk*5 + 1) * N2 + idx] = a1;
    g_spart[(chunk*5 + 2) * N2 + idx] = a2;
    g_spart[(chunk*5 + 3) * N2 + idx] = a3;
    g_spart[(chunk*5 + 4) * N2 + idx] = a4;
}

// ------- K3: combine chunks, derive backward dirs by symmetry, exp --------
__global__ void k_simfin() {
    int idx = blockIdx.x * blockDim.x + threadIdx.x;   // b*SP+s
    if (idx >= N2) return;
    int s  = idx & (SP - 1);
    int sh = s >> 6, sw = s & 63;

    float self = 0.f, fE = 0.f, fSW = 0.f, fS = 0.f, fSE = 0.f;
    #pragma unroll
    for (int cu = 0; cu < NCHUNK; cu++) {
        self += g_spart[(cu*5 + 0) * N2 + idx];
        fE   += g_spart[(cu*5 + 1) * N2 + idx];
        fSW  += g_spart[(cu*5 + 2) * N2 + idx];
        fS   += g_spart[(cu*5 + 3) * N2 + idx];
        fSE  += g_spart[(cu*5 + 4) * N2 + idx];
    }
    bool wOK = (sw > 0), eOK = (sw < SW-1), nOK = (sh > 0), sOK = (sh < SH-1);

    float bW = 0.f, bNE = 0.f, bN = 0.f, bNW = 0.f;
    #pragma unroll
    for (int cu = 0; cu < NCHUNK; cu++) {
        if (wOK)         bW  += g_spart[(cu*5 + 1) * N2 + idx - 1];       // E of s-1
        if (nOK && eOK)  bNE += g_spart[(cu*5 + 2) * N2 + idx - SW + 1];  // SW of s-63
        if (nOK)         bN  += g_spart[(cu*5 + 3) * N2 + idx - SW];      // S of s-64
        if (nOK && wOK)  bNW += g_spart[(cu*5 + 4) * N2 + idx - SW - 1];  // SE of s-65
    }
    g_sim[4*N2 + idx] = expf(-self);
    g_sim[5*N2 + idx] = eOK          ? expf(-fE)  : 0.f;
    g_sim[6*N2 + idx] = (sOK && wOK) ? expf(-fSW) : 0.f;
    g_sim[7*N2 + idx] = sOK          ? expf(-fS)  : 0.f;
    g_sim[8*N2 + idx] = (sOK && eOK) ? expf(-fSE) : 0.f;
    g_sim[3*N2 + idx] = wOK          ? expf(-bW)  : 0.f;
    g_sim[2*N2 + idx] = (nOK && eOK) ? expf(-bNE) : 0.f;
    g_sim[1*N2 + idx] = nOK          ? expf(-bN)  : 0.f;
    g_sim[0*N2 + idx] = (nOK && wOK) ? expf(-bNW) : 0.f;
}

// ---------------- K4: per-pixel main, 4-lane quad per pixel + fused final --
__global__ void k_main(const float* __restrict__ ori, float* __restrict__ out) {
    __shared__ float rp[64], rn[64], rc[64];
    __shared__ int   sh_last;

    int tid = threadIdx.x;
    int j   = tid & 3;                         // lane within quad
    int q   = tid >> 2;                        // quad id within block (0..63)
    int idx = blockIdx.x * 64 + q;             // pixel index b*HW+p
    int b = idx >> 14;
    int p = idx & (HW - 1);
    int h = p >> 7, w = p & 127;
    int sh2 = h >> 1, sw2 = w >> 1;
    size_t sbase = (size_t)b * SP + sh2 * SW + sw2;

    // center probs (all 4 lanes load same 80B -> L1 broadcast)
    const float4* cen = reinterpret_cast<const float4*>(g_prob2 + (size_t)idx * CP);
    float4 pc[5];
    #pragma unroll
    for (int u = 0; u < 5; u++) pc[u] = cen[u];
    float sump = 0.f;
    #pragma unroll
    for (int u = 0; u < 5; u++) sump += pc[u].x + pc[u].y + pc[u].z + pc[u].w;

    float simC = g_sim[4*N2 + sbase];

    // lane j handles k = j, j+4, (j==0: j+8)
    float sim_l[3], pos_l[3], neg_l[3];
    #pragma unroll
    for (int i = 0; i < 3; i++) { sim_l[i] = 0.f; pos_l[i] = 0.f; neg_l[i] = 0.f; }
    #pragma unroll
    for (int i = 0; i < 3; i++) {
        int k = j + 4 * i;
        if (k <= 8) {
            int dr = k / 3 - 1, dc = k % 3 - 1;
            int hn = h + dr, wn = w + dc;
            bool valid = (hn >= 0 && hn < H && wn >= 0 && wn < W);
            if (valid) {
                const float4* qv = reinterpret_cast<const float4*>(
                    g_prob2 + ((size_t)b * HW + hn * W + wn) * CP);
                float d = 0.f;
                #pragma unroll
                for (int u = 0; u < 5; u++) {
                    float4 qq = qv[u];
                    d += pc[u].x*qq.x + pc[u].y*qq.y + pc[u].z*qq.z + pc[u].w*qq.w;
                }
                pos_l[i] = d;
                neg_l[i] = sump - d;           // sumq == 1 for valid neighbors
                int dsh = (hn >> 1) - sh2, dsw = (wn >> 1) - sw2;
                int ks = (dsh + 1) * 3 + (dsw + 1);
                sim_l[i] = (ks == 4) ? 1.0f : g_sim[ks * N2 + sbase];
            } else {
                sim_l[i] = simC;               // pos=neg=0 already
            }
        }
    }

    // gather all 9 (sim,pos,neg) to every lane via shuffles (slot = k>>2 is
    // a compile-time constant per unrolled k; src lane = quad*4 + (k&3))
    float sim[9], pos[9], neg[9];
    int qb = q << 2;
    #pragma unroll
    for (int k = 0; k < 9; k++) {
        int src = qb | (k & 3);
        sim[k] = __shfl_sync(0xffffffffu, sim_l[k >> 2], src);
        pos[k] = __shfl_sync(0xffffffffu, pos_l[k >> 2], src);
        neg[k] = __shfl_sync(0xffffffffu, neg_l[k >> 2], src);
    }

    float lp = 0.f, ln = 0.f, msk = 0.f;
    if (j == 0) {
        float ssum = 0.f;
        #pragma unroll
        for (int k = 0; k < 9; k++) ssum += sim[k];
        out[2 + idx] = ssum * (1.f / 9.f);

        // top-5 by sim descending, stable ties (lower index first)
        bool used[9];
        #pragma unroll
        for (int k = 0; k < 9; k++) used[k] = false;
        #pragma unroll
        for (int t = 0; t < 5; t++) {
            int bi = 0; float bv = -1e30f;
            #pragma unroll
            for (int k = 0; k < 9; k++)
                if (!used[k] && sim[k] > bv) { bv = sim[k]; bi = k; }
            used[bi] = true;
            lp += bv * (-pos[bi]);
        }
        // bottom-4 by sim ascending, stable ties
        bool used2[9];
        #pragma unroll
        for (int k = 0; k < 9; k++) used2[k] = false;
        #pragma unroll
        for (int t = 0; t < 4; t++) {
            int bi = 0; float bv = 1e30f;
            #pragma unroll
            for (int k = 0; k < 9; k++)
                if (!used2[k] && sim[k] < bv) { bv = sim[k]; bi = k; }
            used2[bi] = true;
            ln += (1.f - bv) * (-neg[bi]);
        }
        float f0 = ori[(size_t)b * CF * SP + sh2 * SW + sw2];
        msk = (f0 > 0.f) ? 1.f : 0.f;
        rp[q] = msk * lp; rn[q] = msk * ln; rc[q] = msk;
    }
    __syncthreads();
    #pragma unroll
    for (int o = 32; o > 0; o >>= 1) {
        if (tid < o) { rp[tid] += rp[tid + o]; rn[tid] += rn[tid + o]; rc[tid] += rc[tid + o]; }
        __syncthreads();
    }
    if (tid == 0) {
        g_partial[blockIdx.x]            = (double)rp[0];
        g_partial[NBLK + blockIdx.x]     = (double)rn[0];
        g_partial[2 * NBLK + blockIdx.x] = (double)rc[0];
        __threadfence();
        int v = atomicAdd(&g_count, 1);
        sh_last = (v == NBLK - 1) ? 1 : 0;
    }
    __syncthreads();

    if (sh_last) {
        __shared__ double dp[256], dn[256], dc2[256];
        volatile double* gp = g_partial;
        dp[tid]  = gp[tid]            + gp[tid + 256];
        dn[tid]  = gp[NBLK + tid]     + gp[NBLK + tid + 256];
        dc2[tid] = gp[2 * NBLK + tid] + gp[2 * NBLK + tid + 256];
        __syncthreads();
        #pragma unroll
        for (int o = 128; o > 0; o >>= 1) {
            if (tid < o) { dp[tid] += dp[tid + o]; dn[tid] += dn[tid + o]; dc2[tid] += dc2[tid + o]; }
            __syncthreads();
        }
        if (tid == 0) {
            double cnt = dc2[0];
            out[0] = (float)(dp[0] / (cnt * 5.0));   // /(cnt*(TOP_K+1)) * W_POS
            out[1] = (float)(dn[0] / (cnt * 4.0));   // /(cnt*TOP_K)     * W_NEG
            g_count = 0;                              // reset for graph replay
        }
    }
}

extern "C" void kernel_launch(void* const* d_in, const int* in_sizes, int n_in,
                              void* d_out, int out_size) {
    const float* ori;
    const float* logits;
    if (in_sizes[0] == BB * CF * SP) {
        ori    = (const float*)d_in[0];
        logits = (const float*)d_in[1];
    } else {
        ori    = (const float*)d_in[1];
        logits = (const float*)d_in[0];
    }
    float* out = (float*)d_out;

    k_softmax<<<128, 256>>>(logits);
    dim3 sgrid(N2 / 256, NCHUNK);
    k_simpart<<<sgrid, 256>>>(ori);
    k_simfin<<<N2 / 256, 256>>>();
    k_main<<<NBLK, 256>>>(ori, out);
}

// round 6
// speedup vs baseline: 1.2190x; 1.2190x over previous
#include <cuda_runtime.h>
#include <math.h>

#define BB 2
#define C 19
#define CP 20             // padded channels
#define H 128
#define W 128
#define HW (H*W)          // 16384
#define CF 256
#define SH 64
#define SW 64
#define SP (SH*SW)        // 4096
#define N2 (BB*SP)        // 8192
#define NPIX (BB*HW)      // 32768
#define NCHUNK 8          // feature channel chunks of 32
#define NBLK 128          // main-kernel blocks

// Scratch (static device globals; no allocations)
__device__ float  g_prob2[NPIX*CP];      // padded probs [pixel][20], [19]=0
__device__ float  g_spart[NCHUNK*5*N2];  // [chunk*5+dir][b*SP+s]
__device__ float  g_sim[9*N2];           // [k][b*SP+s]
__device__ float  g_pos[6*NPIX];         // planes: 0=selfdot 1=E 2=SW 3=S 4=SE 5=sump
__device__ double g_partial[3*NBLK];
__device__ int    g_count = 0;

// ================= launch 1: softmax || simpart =================
__device__ __forceinline__ void softmax_work(const float* __restrict__ logits, int idx) {
    int b = idx >> 14;
    int p = idx & (HW - 1);
    const float* x = logits + (size_t)b * C * HW + p;
    float v[CP];
    float m = -1e30f;
    #pragma unroll
    for (int c = 0; c < C; c++) { v[c] = x[(size_t)c * HW]; m = fmaxf(m, v[c]); }
    float s = 0.f;
    #pragma unroll
    for (int c = 0; c < C; c++) { v[c] = expf(v[c] - m); s += v[c]; }
    float inv = 1.f / s;
    #pragma unroll
    for (int c = 0; c < C; c++) v[c] *= inv;
    v[19] = 0.f;
    float4* o = reinterpret_cast<float4*>(g_prob2 + (size_t)idx * CP);
    #pragma unroll
    for (int q = 0; q < 5; q++)
        o[q] = make_float4(v[4*q], v[4*q+1], v[4*q+2], v[4*q+3]);
}

__device__ __forceinline__ void simpart_work(const float* __restrict__ feats,
                                             int idx, int chunk) {
    int b  = idx >> 12;
    int s  = idx & (SP - 1);
    int sh = s >> 6, sw = s & 63;

    bool eOK = (sw < SW-1), sOK = (sh < SH-1), wOK = (sw > 0);
    int dE  = eOK ? 1 : 0;
    int dSW = (sOK && wOK) ? (SW - 1) : 0;
    int dS  = sOK ? SW : 0;
    int dSE = (sOK && eOK) ? (SW + 1) : 0;

    const float* fb = feats + ((size_t)b * CF + chunk * 32) * SP + s;
    float a0 = 0.f, a1 = 0.f, a2 = 0.f, a3 = 0.f, a4 = 0.f;
    #pragma unroll
    for (int ch = 0; ch < 32; ch++) {
        const float* fp = fb + (size_t)ch * SP;
        float f = fp[0];
        float d;
        a0 += f * f;
        d = f - fp[dE];  a1 += d * d;
        d = f - fp[dSW]; a2 += d * d;
        d = f - fp[dS];  a3 += d * d;
        d = f - fp[dSE]; a4 += d * d;
    }
    g_spart[(chunk*5 + 0) * N2 + idx] = a0;
    g_spart[(chunk*5 + 1) * N2 + idx] = a1;
    g_spart[(chunk*5 + 2) * N2 + idx] = a2;
    g_spart[(chunk*5 + 3) * N2 + idx] = a3;
    g_spart[(chunk*5 + 4) * N2 + idx] = a4;
}

__global__ void k_stage1(const float* __restrict__ logits,
                         const float* __restrict__ feats) {
    int bid = blockIdx.x;
    if (bid < 128) {
        softmax_work(logits, bid * 256 + threadIdx.x);
    } else {
        int sblk = bid - 128;                 // 0..255
        int xb = sblk & 31, chunk = sblk >> 5;
        simpart_work(feats, xb * 256 + threadIdx.x, chunk);
    }
}

// ================= launch 2: posdots || simfin =================
__device__ __forceinline__ float dot20(const float4* pc, int nidx) {
    const float4* qv = reinterpret_cast<const float4*>(g_prob2 + (size_t)nidx * CP);
    float d = 0.f;
    #pragma unroll
    for (int u = 0; u < 5; u++) {
        float4 qq = qv[u];
        d += pc[u].x*qq.x + pc[u].y*qq.y + pc[u].z*qq.z + pc[u].w*qq.w;
    }
    return d;
}

__device__ __forceinline__ void pos_work(int t) {
    int half = t >> 15;
    int idx  = t & (NPIX - 1);
    int p = idx & (HW - 1);
    int h = p >> 7, w = p & 127;

    const float4* cen = reinterpret_cast<const float4*>(g_prob2 + (size_t)idx * CP);
    float4 pc[5];
    #pragma unroll
    for (int u = 0; u < 5; u++) pc[u] = cen[u];

    if (half == 0) {
        float sump = 0.f, cdot = 0.f;
        #pragma unroll
        for (int u = 0; u < 5; u++) {
            sump += pc[u].x + pc[u].y + pc[u].z + pc[u].w;
            cdot += pc[u].x*pc[u].x + pc[u].y*pc[u].y + pc[u].z*pc[u].z + pc[u].w*pc[u].w;
        }
        g_pos[0*NPIX + idx] = cdot;
        g_pos[5*NPIX + idx] = sump;
        g_pos[1*NPIX + idx] = (w < W-1)           ? dot20(pc, idx + 1)     : 0.f;
        g_pos[2*NPIX + idx] = (h < H-1 && w > 0)  ? dot20(pc, idx + W - 1) : 0.f;
    } else {
        g_pos[3*NPIX + idx] = (h < H-1)            ? dot20(pc, idx + W)     : 0.f;
        g_pos[4*NPIX + idx] = (h < H-1 && w < W-1) ? dot20(pc, idx + W + 1) : 0.f;
    }
}

__device__ __forceinline__ void simfin_work(int idx) {
    int s  = idx & (SP - 1);
    int sh = s >> 6, sw = s & 63;

    float self = 0.f, fE = 0.f, fSW = 0.f, fS = 0.f, fSE = 0.f;
    #pragma unroll
    for (int cu = 0; cu < NCHUNK; cu++) {
        self += g_spart[(cu*5 + 0) * N2 + idx];
        fE   += g_spart[(cu*5 + 1) * N2 + idx];
        fSW  += g_spart[(cu*5 + 2) * N2 + idx];
        fS   += g_spart[(cu*5 + 3) * N2 + idx];
        fSE  += g_spart[(cu*5 + 4) * N2 + idx];
    }
    bool wOK = (sw > 0), eOK = (sw < SW-1), nOK = (sh > 0), sOK = (sh < SH-1);

    float bW = 0.f, bNE = 0.f, bN = 0.f, bNW = 0.f;
    #pragma unroll
    for (int cu = 0; cu < NCHUNK; cu++) {
        if (wOK)         bW  += g_spart[(cu*5 + 1) * N2 + idx - 1];
        if (nOK && eOK)  bNE += g_spart[(cu*5 + 2) * N2 + idx - SW + 1];
        if (nOK)         bN  += g_spart[(cu*5 + 3) * N2 + idx - SW];
        if (nOK && wOK)  bNW += g_spart[(cu*5 + 4) * N2 + idx - SW - 1];
    }
    g_sim[4*N2 + idx] = expf(-self);
    g_sim[5*N2 + idx] = eOK          ? expf(-fE)  : 0.f;
    g_sim[6*N2 + idx] = (sOK && wOK) ? expf(-fSW) : 0.f;
    g_sim[7*N2 + idx] = sOK          ? expf(-fS)  : 0.f;
    g_sim[8*N2 + idx] = (sOK && eOK) ? expf(-fSE) : 0.f;
    g_sim[3*N2 + idx] = wOK          ? expf(-bW)  : 0.f;
    g_sim[2*N2 + idx] = (nOK && eOK) ? expf(-bNE) : 0.f;
    g_sim[1*N2 + idx] = nOK          ? expf(-bN)  : 0.f;
    g_sim[0*N2 + idx] = (nOK && wOK) ? expf(-bNW) : 0.f;
}

__global__ void k_stage2() {
    int bid = blockIdx.x;
    if (bid < 256) pos_work(bid * 256 + threadIdx.x);
    else           simfin_work((bid - 256) * 256 + threadIdx.x);
}

// ================= launch 3: main + fused final =================
__global__ void k_main(const float* __restrict__ ori, float* __restrict__ out) {
    __shared__ float rp[256], rn[256], rc[256];
    __shared__ int   sh_last;

    int tid = threadIdx.x;
    int idx = blockIdx.x * 256 + tid;          // pixel index
    int b = idx >> 14;
    int p = idx & (HW - 1);
    int h = p >> 7, w = p & 127;
    int sh2 = h >> 1, sw2 = w >> 1;
    size_t sbase = (size_t)b * SP + sh2 * SW + sw2;

    bool nOKp = (h > 0), sOKp = (h < H-1), wOKp = (w > 0), eOKp = (w < W-1);

    float sump = g_pos[5*NPIX + idx];
    float pos[9];
    pos[4] = g_pos[0*NPIX + idx];
    pos[5] = eOKp          ? g_pos[1*NPIX + idx]         : 0.f;
    pos[3] = wOKp          ? g_pos[1*NPIX + idx - 1]     : 0.f;
    pos[7] = sOKp          ? g_pos[3*NPIX + idx]         : 0.f;
    pos[1] = nOKp          ? g_pos[3*NPIX + idx - W]     : 0.f;
    pos[6] = (sOKp && wOKp)? g_pos[2*NPIX + idx]         : 0.f;
    pos[2] = (nOKp && eOKp)? g_pos[2*NPIX + idx - W + 1] : 0.f;
    pos[8] = (sOKp && eOKp)? g_pos[4*NPIX + idx]         : 0.f;
    pos[0] = (nOKp && wOKp)? g_pos[4*NPIX + idx - W - 1] : 0.f;

    float simC = g_sim[4*N2 + sbase];
    float sim[9], neg[9];
    #pragma unroll
    for (int k = 0; k < 9; k++) {
        int dr = k / 3 - 1, dc = k % 3 - 1;
        int hn = h + dr, wn = w + dc;
        bool valid = (hn >= 0 && hn < H && wn >= 0 && wn < W);
        neg[k] = valid ? (sump - pos[k]) : 0.f;   // sumq==1 for valid, 0 for pad
        if (valid) {
            int dsh = (hn >> 1) - sh2, dsw = (wn >> 1) - sw2;
            int ks = (dsh + 1) * 3 + (dsw + 1);
            sim[k] = (ks == 4) ? 1.0f : g_sim[ks * N2 + sbase];
        } else {
            sim[k] = simC;
        }
    }

    float ssum = 0.f;
    #pragma unroll
    for (int k = 0; k < 9; k++) ssum += sim[k];
    out[2 + idx] = ssum * (1.f / 9.f);

    // rank-based stable top-k (matches jax top_k tie-breaking: lower index first)
    int r[9], a[9];
    #pragma unroll
    for (int k = 0; k < 9; k++) { r[k] = 0; a[k] = 0; }
    #pragma unroll
    for (int jj = 0; jj < 9; jj++) {
        #pragma unroll
        for (int kk = jj + 1; kk < 9; kk++) {
            bool l = sim[jj] < sim[kk];
            bool g = sim[jj] > sim[kk];
            r[kk] += !l;    // (sim_j > sim_k) + (equal, j<k)
            r[jj] += l;
            a[kk] += !g;    // (sim_j < sim_k) + (equal, j<k)
            a[jj] += g;
        }
    }
    float lp = 0.f, ln = 0.f;
    #pragma unroll
    for (int k = 0; k < 9; k++) {
        if (r[k] < 5) lp += sim[k] * (-pos[k]);          // top-5 descending
        if (a[k] < 4) ln += (1.f - sim[k]) * (-neg[k]);  // bottom-4 ascending
    }

    float f0  = ori[(size_t)b * CF * SP + sh2 * SW + sw2];
    float msk = (f0 > 0.f) ? 1.f : 0.f;

    rp[tid] = msk * lp; rn[tid] = msk * ln; rc[tid] = msk;
    __syncthreads();
    #pragma unroll
    for (int o = 128; o > 0; o >>= 1) {
        if (tid < o) { rp[tid] += rp[tid + o]; rn[tid] += rn[tid + o]; rc[tid] += rc[tid + o]; }
        __syncthreads();
    }
    if (tid == 0) {
        g_partial[blockIdx.x]            = (double)rp[0];
        g_partial[NBLK + blockIdx.x]     = (double)rn[0];
        g_partial[2 * NBLK + blockIdx.x] = (double)rc[0];
        __threadfence();
        int v = atomicAdd(&g_count, 1);
        sh_last = (v == NBLK - 1) ? 1 : 0;
    }
    __syncthreads();

    if (sh_last) {
        __shared__ double dp[128], dn[128], dc2[128];
        if (tid < 128) {
            volatile double* gp = g_partial;
            dp[tid]  = gp[tid];
            dn[tid]  = gp[NBLK + tid];
            dc2[tid] = gp[2 * NBLK + tid];
        }
        __syncthreads();
        #pragma unroll
        for (int o = 64; o > 0; o >>= 1) {
            if (tid < o) { dp[tid] += dp[tid + o]; dn[tid] += dn[tid + o]; dc2[tid] += dc2[tid + o]; }
            __syncthreads();
        }
        if (tid == 0) {
            double cnt = dc2[0];
            out[0] = (float)(dp[0] / (cnt * 5.0));   // /(cnt*(TOP_K+1)) * W_POS
            out[1] = (float)(dn[0] / (cnt * 4.0));   // /(cnt*TOP_K)     * W_NEG
            g_count = 0;                              // reset for graph replay
        }
    }
}

extern "C" void kernel_launch(void* const* d_in, const int* in_sizes, int n_in,
                              void* d_out, int out_size) {
    const float* ori;
    const float* logits;
    if (in_sizes[0] == BB * CF * SP) {
        ori    = (const float*)d_in[0];
        logits = (const float*)d_in[1];
    } else {
        ori    = (const float*)d_in[1];
        logits = (const float*)d_in[0];
    }
    float* out = (float*)d_out;

    k_stage1<<<384, 256>>>(logits, ori);   // softmax || simpart
    k_stage2<<<288, 256>>>();              // posdots || simfin
    k_main<<<NBLK, 256>>>(ori, out);       // main + fused final
}